// round 14
// baseline (speedup 1.0000x reference)
#include <cuda_runtime.h>
#include <cuda_fp16.h>
#include <math.h>
#include <stdint.h>

#define E    64
#define KTOP 6
#define H    1024
#define F    512
#define SF   2048
#define T    2048
#define CAP  384

#if !defined(__CUDA_ARCH__) || defined(__CUDA_ARCH_FEAT_SM103_ALL) || \
    defined(__CUDA_ARCH_FEAT_SM100_ALL) || defined(__CUDA_ARCH_FEAT_SM101_ALL) || \
    defined(__CUDA_ARCH_SPECIFIC__)
#define TC_OK 1
#else
#define TC_OK 0
#endif

__device__ int    g_cnt[E];
__device__ int    g_slot_token[E * CAP];
__device__ int    g_pair_slot[T * KTOP];
__device__ float  g_pair_w[T * KTOP];
__device__ __half g_midh[(size_t)E * CAP * F];
__device__ __half g_yh[(size_t)E * CAP * H];
__device__ __half g_smidh[(size_t)T * SF];
__device__ __half g_xrh[(size_t)T * H];
__device__ __half g_sw1h[(size_t)SF * H];
__device__ __half g_sw2h[(size_t)H * SF];
__device__ __half g_w1th[(size_t)E * F * H];
__device__ __half g_w2th[(size_t)E * H * F];

__device__ __forceinline__ float gelu_tanh(float x) {
    float u = 0.7978845608028654f * (x + 0.044715f * x * x * x);
    return 0.5f * x * (1.0f + tanhf(u));
}
__device__ __forceinline__ uint32_t pack_h2(float hi, float lo) {
    uint32_t r;
    asm("cvt.rn.f16x2.f32 %0, %1, %2;" : "=r"(r) : "f"(hi), "f"(lo));
    return r;
}

#if TC_OK
__device__ __forceinline__ uint32_t smem_u32(const void* p) {
    uint32_t a;
    asm("{ .reg .u64 t; cvta.to.shared.u64 t, %1; cvt.u32.u64 %0, t; }" : "=r"(a) : "l"(p));
    return a;
}
__device__ __forceinline__ uint32_t elect_one() {
    uint32_t pred;
    asm volatile("{\n\t.reg .pred p;\n\telect.sync _|p, 0xFFFFFFFF;\n\tselp.b32 %0, 1, 0, p;\n\t}" : "=r"(pred));
    return pred;
}
__device__ __forceinline__ void cpasync16(uint32_t dst, const void* src, uint32_t sz) {
    asm volatile("cp.async.cg.shared.global [%0], [%1], 16, %2;" :: "r"(dst), "l"(src), "r"(sz) : "memory");
}
__device__ __forceinline__ void cp_commit() { asm volatile("cp.async.commit_group;" ::: "memory"); }
__device__ __forceinline__ void cp_wait1()  { asm volatile("cp.async.wait_group 1;" ::: "memory"); }
__device__ __forceinline__ void mbar_init(uint32_t mbar, uint32_t cnt) {
    asm volatile("mbarrier.init.shared.b64 [%0], %1;" :: "r"(mbar), "r"(cnt) : "memory");
}
__device__ __forceinline__ void mbar_wait(uint32_t mbar, uint32_t parity) {
    asm volatile(
        "{\n\t.reg .pred P;\nW_%=:\n\t"
        "mbarrier.try_wait.parity.acquire.cta.shared::cta.b64 P, [%0], %1, 0x989680;\n\t"
        "@P bra.uni D_%=;\n\tbra.uni W_%=;\nD_%=:\n\t}"
        :: "r"(mbar), "r"(parity) : "memory");
}
__device__ __forceinline__ void tc_alloc(uint32_t s, uint32_t n) {
    asm volatile("tcgen05.alloc.cta_group::1.sync.aligned.shared::cta.b32 [%0], %1;" :: "r"(s), "r"(n) : "memory");
}
__device__ __forceinline__ void tc_relinquish() {
    asm volatile("tcgen05.relinquish_alloc_permit.cta_group::1.sync.aligned;");
}
__device__ __forceinline__ void tc_dealloc(uint32_t t, uint32_t n) {
    asm volatile("tcgen05.dealloc.cta_group::1.sync.aligned.b32 %0, %1;" :: "r"(t), "r"(n));
}
__device__ __forceinline__ void tc_commit(uint32_t mbar) {
    asm volatile("tcgen05.commit.cta_group::1.mbarrier::arrive::one.shared::cluster.b64 [%0];" :: "r"(mbar) : "memory");
}
__device__ __forceinline__ void fence_async()   { asm volatile("fence.proxy.async.shared::cta;" ::: "memory"); }
__device__ __forceinline__ void tc_fence_after(){ asm volatile("tcgen05.fence::after_thread_sync;" ::: "memory"); }
__device__ __forceinline__ void tc_wait_ld()    { asm volatile("tcgen05.wait::ld.sync.aligned;" ::: "memory"); }
__device__ __forceinline__ void mma_f16_ss(uint32_t d, uint64_t ad, uint64_t bd, uint32_t idesc, uint32_t en) {
    asm volatile(
        "{\n\t.reg .pred p;\n\tsetp.ne.u32 p, %5, 0;\n\t"
        "tcgen05.mma.cta_group::1.kind::f16 [%0], %1, %2, %3, {%4, %4, %4, %4}, p;\n\t}"
        :: "r"(d), "l"(ad), "l"(bd), "r"(idesc), "r"(0u), "r"(en) : "memory");
}
__device__ __forceinline__ void ldtm32(uint32_t* r, uint32_t addr) {
    asm volatile(
        "tcgen05.ld.sync.aligned.32x32b.x32.b32 "
        "{%0, %1, %2, %3, %4, %5, %6, %7, %8, %9, %10, %11, %12, %13, %14, %15, "
        "%16, %17, %18, %19, %20, %21, %22, %23, %24, %25, %26, %27, %28, %29, %30, %31}, [%32];"
        : "=r"(r[0]), "=r"(r[1]), "=r"(r[2]), "=r"(r[3]), "=r"(r[4]), "=r"(r[5]), "=r"(r[6]), "=r"(r[7]),
          "=r"(r[8]), "=r"(r[9]), "=r"(r[10]), "=r"(r[11]), "=r"(r[12]), "=r"(r[13]), "=r"(r[14]), "=r"(r[15]),
          "=r"(r[16]), "=r"(r[17]), "=r"(r[18]), "=r"(r[19]), "=r"(r[20]), "=r"(r[21]), "=r"(r[22]), "=r"(r[23]),
          "=r"(r[24]), "=r"(r[25]), "=r"(r[26]), "=r"(r[27]), "=r"(r[28]), "=r"(r[29]), "=r"(r[30]), "=r"(r[31])
        : "r"(addr));
}
__device__ __forceinline__ uint32_t sw128(uint32_t b) { return b ^ ((b >> 3) & 0x70); }
#define DESCK      0x4000404000010000ull
#define IDESC_H256 0x8400010u
#define IDESC_H128 0x8200010u
#endif

__global__ void zero_cnt_kernel(int* cnt) {
    if (threadIdx.x < E) cnt[threadIdx.x] = 0;
}

// transpose + cvt: src fp32 [E][R][C] -> dst fp16 [E][C][R]
__global__ __launch_bounds__(256) void tcvt_kernel(
    const float* __restrict__ src, __half* __restrict__ dst, int R, int Cc)
{
    __shared__ float tile[32][133];
    int e = blockIdx.z;
    const float* S = src + (size_t)e * R * Cc;
    __half*      D = dst + (size_t)e * R * Cc;
    int r0 = blockIdx.y * 32, c0 = blockIdx.x * 128;
    int tx = threadIdx.x & 31, ty = threadIdx.x >> 5;
    #pragma unroll
    for (int i = 0; i < 4; i++) {
        int r = ty + 8 * i;
        float4 v = *(const float4*)(S + (size_t)(r0 + r) * Cc + c0 + tx * 4);
        tile[r][tx * 4 + 0] = v.x; tile[r][tx * 4 + 1] = v.y;
        tile[r][tx * 4 + 2] = v.z; tile[r][tx * 4 + 3] = v.w;
    }
    __syncthreads();
    int rx = threadIdx.x & 7, cy = threadIdx.x >> 3;
    #pragma unroll
    for (int i = 0; i < 4; i++) {
        int c = cy + 32 * i;
        uint2 o = make_uint2(
            pack_h2(tile[rx * 4 + 1][c], tile[rx * 4 + 0][c]),
            pack_h2(tile[rx * 4 + 3][c], tile[rx * 4 + 2][c]));
        *(uint2*)(D + (size_t)(c0 + c) * R + r0 + rx * 4) = o;
    }
}

__global__ __launch_bounds__(256) void prep_kernel(
    const float* __restrict__ sw1, __half* __restrict__ sw1h,
    const float* __restrict__ sw2, __half* __restrict__ sw2h)
{
    int i = blockIdx.x * 256 + threadIdx.x;
    float4 a = ((const float4*)sw1)[i];
    ((uint2*)sw1h)[i] = make_uint2(pack_h2(a.y, a.x), pack_h2(a.w, a.z));
    float4 b = ((const float4*)sw2)[i];
    ((uint2*)sw2h)[i] = make_uint2(pack_h2(b.y, b.x), pack_h2(b.w, b.z));
}

__global__ __launch_bounds__(256) void router2_kernel(
    const float* __restrict__ x, const float* __restrict__ rw,
    const float* __restrict__ bias,
    int* __restrict__ cnt, int* __restrict__ slot_token,
    int* __restrict__ pair_slot, float* __restrict__ pair_w,
    __half* __restrict__ xrh)
{
    const int tb = blockIdx.x * 8;
    __shared__ float xs[8][H];
    __shared__ float sc[8][E];
    __shared__ float sb[E];
    const int tid = threadIdx.x;
    const int warp = tid >> 5, lane = tid & 31;

    for (int i = tid; i < 8 * H / 4; i += 256) {
        int row = i >> 8, c4 = i & 255;
        float4 v = ((const float4*)(x + (size_t)(tb + row) * H))[c4];
        ((float4*)xs[row])[c4] = v;
        ((uint2*)(xrh + (size_t)(tb + row) * H))[c4] =
            make_uint2(pack_h2(v.y, v.x), pack_h2(v.w, v.z));
    }
    if (tid < E) sb[tid] = bias[tid];
    __syncthreads();

    for (int q = 0; q < 8; q++) {
        int e = warp * 8 + q;
        const float* wrow = rw + (size_t)e * H;
        float s[8];
        #pragma unroll
        for (int tt = 0; tt < 8; tt++) s[tt] = 0.f;
        for (int i = lane; i < H; i += 32) {
            float wv = wrow[i];
            #pragma unroll
            for (int tt = 0; tt < 8; tt++) s[tt] += xs[tt][i] * wv;
        }
        #pragma unroll
        for (int o = 16; o; o >>= 1)
            #pragma unroll
            for (int tt = 0; tt < 8; tt++) s[tt] += __shfl_xor_sync(0xffffffffu, s[tt], o);
        if (lane == 0) {
            #pragma unroll
            for (int tt = 0; tt < 8; tt++) sc[tt][e] = 1.f / (1.f + expf(-s[tt]));
        }
    }
    __syncthreads();

    if (tid < 8) {
        int t = tb + tid;
        unsigned long long used = 0ull;
        int idx[KTOP]; float tsc[KTOP]; float sum = 0.f;
        #pragma unroll
        for (int k = 0; k < KTOP; k++) {
            float best = -1e30f; int bi = 0;
            for (int e = 0; e < E; e++) {
                if (used & (1ull << e)) continue;
                float v = sc[tid][e] + sb[e];
                if (v > best) { best = v; bi = e; }
            }
            used |= 1ull << bi; idx[k] = bi; tsc[k] = sc[tid][bi]; sum += sc[tid][bi];
        }
        float inv = 1.f / (sum + 1e-20f);
        #pragma unroll
        for (int k = 0; k < KTOP; k++) {
            int e = idx[k];
            int pos = atomicAdd(&cnt[e], 1);
            float w = tsc[k] * inv;
            int slot;
            if (pos < CAP) { slot = e * CAP + pos; slot_token[slot] = t; }
            else           { slot = 0; w = 0.f; }
            pair_slot[t * KTOP + k] = slot;
            pair_w[t * KTOP + k]    = w;
        }
    }
}

// ===== gemm_tc: fp16 A & B (K-major), K-chunk 64, 2-stage pipeline, 2 CTAs/SM =====
template<bool GATHER, bool GELU, bool HOUT, int NTILE>
__global__ __launch_bounds__(256) void gemm_tc(
    const __half* __restrict__ Aall, long long sAe, int ldA,
    const __half* __restrict__ Ball, long long sBe,
    void* __restrict__ Call, long long sCe, int ldC,
    int Kdim, int Ncols,
    const int* __restrict__ cnts, int Mmax,
    const int* __restrict__ tokall)
{
    const int e  = blockIdx.z;
    const int m0 = blockIdx.y * 128;
    const int n0 = blockIdx.x * NTILE;
    int M = Mmax;
    if (cnts) { M = min(cnts[e], Mmax); if (m0 >= M) return; }
    const __half* B = Ball + (long long)e * sBe;

#if TC_OK
    constexpr int ABYTES = 16384;
    constexpr int BBYTES = NTILE * 128;
    constexpr int STAGE  = ABYTES + BBYTES;
    constexpr int NB     = NTILE / 32;
    constexpr uint32_t IDESC = (NTILE == 256) ? IDESC_H256 : IDESC_H128;

    extern __shared__ char smraw_c[];
    const uint32_t sbase = (smem_u32(smraw_c) + 1023u) & ~1023u;
    const uint32_t ctrl  = sbase + 2 * STAGE;
    const int tid = threadIdx.x, warp = tid >> 5, lane = tid & 31;

    if (warp == 0) { tc_alloc(ctrl, 256); tc_relinquish(); }
    if (tid == 0) {
        #pragma unroll
        for (int j = 0; j < 4; j++) mbar_init(ctrl + 8 + 8 * j, 1);
    }
    __syncthreads();
    uint32_t tmem;
    asm volatile("ld.shared.b32 %0, [%1];" : "=r"(tmem) : "r"(ctrl));

    const __half* aptr[4]; uint32_t a_sts[4], a_ok[4];
    #pragma unroll
    for (int j = 0; j < 4; j++) {
        int g = tid + j * 256;
        int m = g >> 3, k8 = (g & 7) * 8;
        a_sts[j] = sw128(m * 128 + k8 * 2);
        if (GATHER) {
            int tok = (m0 + m < M) ? tokall[e * CAP + m0 + m] : -1;
            a_ok[j] = (tok >= 0) ? 16u : 0u;
            aptr[j] = (tok >= 0) ? (Aall + (long long)tok * ldA + k8) : Aall;
        } else {
            a_ok[j] = 16u;
            aptr[j] = Aall + (long long)e * sAe + (long long)(m0 + m) * ldA + k8;
        }
    }
    const __half* bptr[NB]; uint32_t b_sts[NB];
    #pragma unroll
    for (int j = 0; j < NB; j++) {
        int g = tid + j * 256;
        int n = g >> 3, k8 = (g & 7) * 8;
        b_sts[j] = sw128(n * 128 + k8 * 2);
        bptr[j]  = B + (long long)(n0 + n) * Kdim + k8;
    }
    const int ntiles = Kdim >> 6;

    auto issue = [&](int it) {
        uint32_t base = sbase + (it & 1) * STAGE;
        long long ka = (long long)it * 64;
        #pragma unroll
        for (int j = 0; j < 4; j++) cpasync16(base + a_sts[j], aptr[j] + ka, a_ok[j]);
        #pragma unroll
        for (int j = 0; j < NB; j++) cpasync16(base + ABYTES + b_sts[j], bptr[j] + ka, 16u);
    };

    issue(0); cp_commit();
    issue(1); cp_commit();

    for (int it = 0; it < ntiles; ++it) {
        cp_wait1();                 // loads(it) retired
        __syncthreads();
        if (warp == 0 && elect_one()) {
            fence_async();
            uint32_t sa = sbase + (it & 1) * STAGE;
            uint64_t ad = DESCK | ((sa >> 4) & 0x3FFFu);
            uint64_t bd = DESCK | (((sa + ABYTES) >> 4) & 0x3FFFu);
            #pragma unroll
            for (int s = 0; s < 4; s++)
                mma_f16_ss(tmem, ad + 2 * s, bd + 2 * s, IDESC, (it | s) != 0);
            tc_commit(ctrl + 8 + 8 * (it & 3));
        }
        if (it + 2 < ntiles) {
            mbar_wait(ctrl + 8 + 8 * (it & 3), (it >> 2) & 1);  // MMA(it) done -> buffer free
            issue(it + 2);
        }
        cp_commit();
    }
    { int p = ntiles - 1; mbar_wait(ctrl + 8 + 8 * (p & 3), (p >> 2) & 1); }
    tc_fence_after();

    {
        const int w4 = warp & 3, half = warp >> 2;
        const int row = m0 + w4 * 32 + lane;
        #pragma unroll
        for (int i = 0; i < NTILE / 64; i++) {
            int c0 = half * (NTILE / 2) + i * 32;
            uint32_t r[32];
            ldtm32(r, tmem + c0);
            tc_wait_ld();
            float fv[32];
            #pragma unroll
            for (int q = 0; q < 32; q++) {
                float v = __uint_as_float(r[q]);
                fv[q] = GELU ? gelu_tanh(v) : v;
            }
            if (HOUT) {
                __half* crow = (__half*)Call + (long long)e * sCe + (long long)row * ldC + n0;
                #pragma unroll
                for (int q = 0; q < 4; q++) {
                    uint4 o = make_uint4(
                        pack_h2(fv[q*8+1], fv[q*8+0]), pack_h2(fv[q*8+3], fv[q*8+2]),
                        pack_h2(fv[q*8+5], fv[q*8+4]), pack_h2(fv[q*8+7], fv[q*8+6]));
                    *(uint4*)(crow + c0 + q * 8) = o;
                }
            } else {
                float* crow = (float*)Call + (long long)e * sCe + (long long)row * ldC + n0;
                #pragma unroll
                for (int q = 0; q < 8; q++)
                    *(float4*)(crow + c0 + q * 4) =
                        make_float4(fv[q*4], fv[q*4+1], fv[q*4+2], fv[q*4+3]);
            }
        }
    }
    __syncthreads();
    if (warp == 0) tc_dealloc(tmem, 256);
#else
    const int tid = threadIdx.x;
    const int row = m0 + (tid >> 1);
    const int nh  = (tid & 1) * (NTILE / 2);
    const __half* arow;
    if (GATHER) {
        int tok = (row < M) ? tokall[e * CAP + row] : -1;
        arow = (tok >= 0) ? (Aall + (long long)tok * ldA) : nullptr;
    } else arow = Aall + (long long)e * sAe + (long long)row * ldA;
    for (int c = 0; c < NTILE / 64; c++) {
        float acc[32];
        #pragma unroll
        for (int q = 0; q < 32; q++) acc[q] = 0.f;
        int nb = n0 + nh + c * 32;
        for (int k = 0; k < Kdim; k++) {
            float a = arow ? __half2float(arow[k]) : 0.f;
            for (int q = 0; q < 32; q++)
                acc[q] += a * __half2float(B[(long long)(nb + q) * Kdim + k]);
        }
        for (int q = 0; q < 32; q++) {
            float v = acc[q];
            if (GELU) v = gelu_tanh(v);
            if (HOUT) ((__half*)Call)[(long long)e * sCe + (long long)row * ldC + nb + q] = __float2half(v);
            else      ((float*)Call)[(long long)e * sCe + (long long)row * ldC + nb + q] = v;
        }
    }
#endif
}

__global__ __launch_bounds__(256) void combine_kernel(
    float* __restrict__ out, const __half* __restrict__ y,
    const int* __restrict__ pair_slot, const float* __restrict__ pair_w)
{
    int t = blockIdx.x;
    int slot[KTOP]; float w[KTOP];
    #pragma unroll
    for (int k = 0; k < KTOP; k++) {
        slot[k] = pair_slot[t * KTOP + k];
        w[k]    = pair_w[t * KTOP + k];
    }
    int h4 = threadIdx.x;
    float4 acc = *(float4*)(out + (size_t)t * H + h4 * 4);
    #pragma unroll
    for (int k = 0; k < KTOP; k++) {
        uint2 p = *(const uint2*)(y + (size_t)slot[k] * H + h4 * 4);
        __half2 a = *(__half2*)&p.x, b = *(__half2*)&p.y;
        acc.x += w[k] * __low2float(a);  acc.y += w[k] * __high2float(a);
        acc.z += w[k] * __low2float(b);  acc.w += w[k] * __high2float(b);
    }
    *(float4*)(out + (size_t)t * H + h4 * 4) = acc;
}

extern "C" void kernel_launch(void* const* d_in, const int* in_sizes, int n_in,
                              void* d_out, int out_size)
{
    const float* x   = (const float*)d_in[0];
    const float* rw  = (const float*)d_in[1];
    const float* eb  = (const float*)d_in[2];
    const float* w1  = (const float*)d_in[3];
    const float* w2  = (const float*)d_in[4];
    const float* sw1 = (const float*)d_in[5];
    const float* sw2 = (const float*)d_in[6];
    float* out = (float*)d_out;

    void *pcnt, *ptok, *pps, *ppw, *pmid, *py, *psmid, *pxr, *ps1, *ps2, *pw1t, *pw2t;
    cudaGetSymbolAddress(&pcnt,  g_cnt);
    cudaGetSymbolAddress(&ptok,  g_slot_token);
    cudaGetSymbolAddress(&pps,   g_pair_slot);
    cudaGetSymbolAddress(&ppw,   g_pair_w);
    cudaGetSymbolAddress(&pmid,  g_midh);
    cudaGetSymbolAddress(&py,    g_yh);
    cudaGetSymbolAddress(&psmid, g_smidh);
    cudaGetSymbolAddress(&pxr,   g_xrh);
    cudaGetSymbolAddress(&ps1,   g_sw1h);
    cudaGetSymbolAddress(&ps2,   g_sw2h);
    cudaGetSymbolAddress(&pw1t,  g_w1th);
    cudaGetSymbolAddress(&pw2t,  g_w2th);

    int*    cnt       = (int*)pcnt;
    int*    slot_tok  = (int*)ptok;
    int*    pair_slot = (int*)pps;
    float*  pair_w    = (float*)ppw;
    __half* midh      = (__half*)pmid;
    __half* yh        = (__half*)py;
    __half* smidh     = (__half*)psmid;
    __half* xrh       = (__half*)pxr;
    __half* sw1h      = (__half*)ps1;
    __half* sw2h      = (__half*)ps2;
    __half* w1th      = (__half*)pw1t;
    __half* w2th      = (__half*)pw2t;

    const int SM256 = 2 * (16384 + 256 * 128) + 1024 + 64;   // 99392 -> 2 CTAs/SM
    const int SM128 = 2 * (16384 + 128 * 128) + 1024 + 64;   // 66624

    static cudaStream_t s1 = nullptr, s2 = nullptr;
    static cudaEvent_t evF, evW1, evW2, evR, evS;
    if (!s1) {
        cudaStreamCreateWithFlags(&s1, cudaStreamNonBlocking);
        cudaStreamCreateWithFlags(&s2, cudaStreamNonBlocking);
        cudaEventCreateWithFlags(&evF,  cudaEventDisableTiming);
        cudaEventCreateWithFlags(&evW1, cudaEventDisableTiming);
        cudaEventCreateWithFlags(&evW2, cudaEventDisableTiming);
        cudaEventCreateWithFlags(&evR,  cudaEventDisableTiming);
        cudaEventCreateWithFlags(&evS,  cudaEventDisableTiming);
        cudaFuncSetAttribute(gemm_tc<true,  true,  true,  256>, cudaFuncAttributeMaxDynamicSharedMemorySize, SM256);
        cudaFuncSetAttribute(gemm_tc<false, false, true,  256>, cudaFuncAttributeMaxDynamicSharedMemorySize, SM256);
        cudaFuncSetAttribute(gemm_tc<false, true,  true,  256>, cudaFuncAttributeMaxDynamicSharedMemorySize, SM256);
        cudaFuncSetAttribute(gemm_tc<false, false, false, 128>, cudaFuncAttributeMaxDynamicSharedMemorySize, SM128);
    }

    zero_cnt_kernel<<<1, 64>>>(cnt);
    cudaEventRecord(evF, 0);
    cudaStreamWaitEvent(s1, evF, 0);
    cudaStreamWaitEvent(s2, evF, 0);

    router2_kernel<<<T / 8, 256>>>(x, rw, eb, cnt, slot_tok, pair_slot, pair_w, xrh);
    cudaEventRecord(evR, 0);

    tcvt_kernel<<<dim3(F / 128, H / 32, E), 256, 0, s1>>>(w1, w1th, H, F);
    cudaEventRecord(evW1, s1);

    cudaStreamWaitEvent(0, evW1, 0);
    gemm_tc<true, true, true, 256><<<dim3(F / 256, CAP / 128, E), 256, SM256>>>(
        xrh, 0LL, H, w1th, (long long)F * H,
        midh, (long long)CAP * F, F, H, F, cnt, CAP, slot_tok);

    tcvt_kernel<<<dim3(H / 128, F / 32, E), 256, 0, s1>>>(w2, w2th, F, H);
    cudaEventRecord(evW2, s1);

    cudaStreamWaitEvent(0, evW2, 0);
    gemm_tc<false, false, true, 256><<<dim3(H / 256, CAP / 128, E), 256, SM256>>>(
        midh, (long long)CAP * F, F, w2th, (long long)H * F,
        yh, (long long)CAP * H, H, F, H, cnt, CAP, slot_tok);

    prep_kernel<<<SF * H / 4 / 256, 256, 0, s2>>>(sw1, sw1h, sw2, sw2h);
    cudaStreamWaitEvent(s2, evR, 0);
    gemm_tc<false, true, true, 256><<<dim3(SF / 256, T / 128, 1), 256, SM256, s2>>>(
        xrh, 0LL, H, sw1h, 0LL, smidh, 0LL, SF, H, SF, nullptr, T, nullptr);
    gemm_tc<false, false, false, 128><<<dim3(H / 128, T / 128, 1), 256, SM128, s2>>>(
        smidh, 0LL, SF, sw2h, 0LL, out, 0LL, H, SF, H, nullptr, T, nullptr);
    cudaEventRecord(evS, s2);

    cudaStreamWaitEvent(0, evS, 0);
    combine_kernel<<<T, 256>>>(out, yh, pair_slot, pair_w);
}

// round 15
// speedup vs baseline: 1.0288x; 1.0288x over previous
#include <cuda_runtime.h>
#include <cuda_fp16.h>
#include <math.h>
#include <stdint.h>

#define E    64
#define KTOP 6
#define H    1024
#define F    512
#define SF   2048
#define T    2048
#define CAP  384

#if !defined(__CUDA_ARCH__) || defined(__CUDA_ARCH_FEAT_SM103_ALL) || \
    defined(__CUDA_ARCH_FEAT_SM100_ALL) || defined(__CUDA_ARCH_FEAT_SM101_ALL) || \
    defined(__CUDA_ARCH_SPECIFIC__)
#define TC_OK 1
#else
#define TC_OK 0
#endif

__device__ int    g_cnt[E];
__device__ int    g_slot_token[E * CAP];
__device__ int    g_pair_slot[T * KTOP];
__device__ float  g_pair_w[T * KTOP];
__device__ __half g_midh[(size_t)E * CAP * F];
__device__ __half g_yh[(size_t)E * CAP * H];
__device__ __half g_smidh[(size_t)T * SF];
__device__ __half g_xrh[(size_t)T * H];
__device__ __half g_sw1h[(size_t)SF * H];
__device__ __half g_sw2h[(size_t)H * SF];
__device__ __half g_w1th[(size_t)E * F * H];
__device__ __half g_w2th[(size_t)E * H * F];

__device__ __forceinline__ float gelu_tanh(float x) {
    float u = 0.7978845608028654f * (x + 0.044715f * x * x * x);
    return 0.5f * x * (1.0f + tanhf(u));
}
__device__ __forceinline__ uint32_t pack_h2(float hi, float lo) {
    uint32_t r;
    asm("cvt.rn.f16x2.f32 %0, %1, %2;" : "=r"(r) : "f"(hi), "f"(lo));
    return r;
}

#if TC_OK
__device__ __forceinline__ uint32_t smem_u32(const void* p) {
    uint32_t a;
    asm("{ .reg .u64 t; cvta.to.shared.u64 t, %1; cvt.u32.u64 %0, t; }" : "=r"(a) : "l"(p));
    return a;
}
__device__ __forceinline__ uint32_t elect_one() {
    uint32_t pred;
    asm volatile("{\n\t.reg .pred p;\n\telect.sync _|p, 0xFFFFFFFF;\n\tselp.b32 %0, 1, 0, p;\n\t}" : "=r"(pred));
    return pred;
}
__device__ __forceinline__ void cpasync16(uint32_t dst, const void* src, uint32_t sz) {
    asm volatile("cp.async.cg.shared.global [%0], [%1], 16, %2;" :: "r"(dst), "l"(src), "r"(sz) : "memory");
}
__device__ __forceinline__ void cp_commit() { asm volatile("cp.async.commit_group;" ::: "memory"); }
__device__ __forceinline__ void cp_wait2()  { asm volatile("cp.async.wait_group 2;" ::: "memory"); }
__device__ __forceinline__ void mbar_init(uint32_t mbar, uint32_t cnt) {
    asm volatile("mbarrier.init.shared.b64 [%0], %1;" :: "r"(mbar), "r"(cnt) : "memory");
}
__device__ __forceinline__ void mbar_wait(uint32_t mbar, uint32_t parity) {
    asm volatile(
        "{\n\t.reg .pred P;\nW_%=:\n\t"
        "mbarrier.try_wait.parity.acquire.cta.shared::cta.b64 P, [%0], %1, 0x989680;\n\t"
        "@P bra.uni D_%=;\n\tbra.uni W_%=;\nD_%=:\n\t}"
        :: "r"(mbar), "r"(parity) : "memory");
}
__device__ __forceinline__ void tc_alloc(uint32_t s, uint32_t n) {
    asm volatile("tcgen05.alloc.cta_group::1.sync.aligned.shared::cta.b32 [%0], %1;" :: "r"(s), "r"(n) : "memory");
}
__device__ __forceinline__ void tc_relinquish() {
    asm volatile("tcgen05.relinquish_alloc_permit.cta_group::1.sync.aligned;");
}
__device__ __forceinline__ void tc_dealloc(uint32_t t, uint32_t n) {
    asm volatile("tcgen05.dealloc.cta_group::1.sync.aligned.b32 %0, %1;" :: "r"(t), "r"(n));
}
__device__ __forceinline__ void tc_commit(uint32_t mbar) {
    asm volatile("tcgen05.commit.cta_group::1.mbarrier::arrive::one.shared::cluster.b64 [%0];" :: "r"(mbar) : "memory");
}
__device__ __forceinline__ void fence_async()   { asm volatile("fence.proxy.async.shared::cta;" ::: "memory"); }
__device__ __forceinline__ void tc_fence_after(){ asm volatile("tcgen05.fence::after_thread_sync;" ::: "memory"); }
__device__ __forceinline__ void tc_wait_ld()    { asm volatile("tcgen05.wait::ld.sync.aligned;" ::: "memory"); }
__device__ __forceinline__ void mma_f16_ss(uint32_t d, uint64_t ad, uint64_t bd, uint32_t idesc, uint32_t en) {
    asm volatile(
        "{\n\t.reg .pred p;\n\tsetp.ne.u32 p, %5, 0;\n\t"
        "tcgen05.mma.cta_group::1.kind::f16 [%0], %1, %2, %3, {%4, %4, %4, %4}, p;\n\t}"
        :: "r"(d), "l"(ad), "l"(bd), "r"(idesc), "r"(0u), "r"(en) : "memory");
}
__device__ __forceinline__ void ldtm32(uint32_t* r, uint32_t addr) {
    asm volatile(
        "tcgen05.ld.sync.aligned.32x32b.x32.b32 "
        "{%0, %1, %2, %3, %4, %5, %6, %7, %8, %9, %10, %11, %12, %13, %14, %15, "
        "%16, %17, %18, %19, %20, %21, %22, %23, %24, %25, %26, %27, %28, %29, %30, %31}, [%32];"
        : "=r"(r[0]), "=r"(r[1]), "=r"(r[2]), "=r"(r[3]), "=r"(r[4]), "=r"(r[5]), "=r"(r[6]), "=r"(r[7]),
          "=r"(r[8]), "=r"(r[9]), "=r"(r[10]), "=r"(r[11]), "=r"(r[12]), "=r"(r[13]), "=r"(r[14]), "=r"(r[15]),
          "=r"(r[16]), "=r"(r[17]), "=r"(r[18]), "=r"(r[19]), "=r"(r[20]), "=r"(r[21]), "=r"(r[22]), "=r"(r[23]),
          "=r"(r[24]), "=r"(r[25]), "=r"(r[26]), "=r"(r[27]), "=r"(r[28]), "=r"(r[29]), "=r"(r[30]), "=r"(r[31])
        : "r"(addr));
}
__device__ __forceinline__ uint32_t sw128(uint32_t b) { return b ^ ((b >> 3) & 0x70); }
#define DESCK      0x4000404000010000ull
#define IDESC_H256 0x8400010u
#define IDESC_H128 0x8200010u
#endif

__global__ void zero_cnt_kernel(int* cnt) {
    if (threadIdx.x < E) cnt[threadIdx.x] = 0;
}

// transpose + cvt: src fp32 [E][R][C] -> dst fp16 [E][C][R]
__global__ __launch_bounds__(256) void tcvt_kernel(
    const float* __restrict__ src, __half* __restrict__ dst, int R, int Cc)
{
    __shared__ float tile[32][133];
    int e = blockIdx.z;
    const float* S = src + (size_t)e * R * Cc;
    __half*      D = dst + (size_t)e * R * Cc;
    int r0 = blockIdx.y * 32, c0 = blockIdx.x * 128;
    int tx = threadIdx.x & 31, ty = threadIdx.x >> 5;
    #pragma unroll
    for (int i = 0; i < 4; i++) {
        int r = ty + 8 * i;
        float4 v = *(const float4*)(S + (size_t)(r0 + r) * Cc + c0 + tx * 4);
        tile[r][tx * 4 + 0] = v.x; tile[r][tx * 4 + 1] = v.y;
        tile[r][tx * 4 + 2] = v.z; tile[r][tx * 4 + 3] = v.w;
    }
    __syncthreads();
    int rx = threadIdx.x & 7, cy = threadIdx.x >> 3;
    #pragma unroll
    for (int i = 0; i < 4; i++) {
        int c = cy + 32 * i;
        uint2 o = make_uint2(
            pack_h2(tile[rx * 4 + 1][c], tile[rx * 4 + 0][c]),
            pack_h2(tile[rx * 4 + 3][c], tile[rx * 4 + 2][c]));
        *(uint2*)(D + (size_t)(c0 + c) * R + r0 + rx * 4) = o;
    }
}

__global__ __launch_bounds__(256) void prep_kernel(
    const float* __restrict__ sw1, __half* __restrict__ sw1h,
    const float* __restrict__ sw2, __half* __restrict__ sw2h)
{
    int i = blockIdx.x * 256 + threadIdx.x;
    float4 a = ((const float4*)sw1)[i];
    ((uint2*)sw1h)[i] = make_uint2(pack_h2(a.y, a.x), pack_h2(a.w, a.z));
    float4 b = ((const float4*)sw2)[i];
    ((uint2*)sw2h)[i] = make_uint2(pack_h2(b.y, b.x), pack_h2(b.w, b.z));
}

__global__ __launch_bounds__(256) void router2_kernel(
    const float* __restrict__ x, const float* __restrict__ rw,
    const float* __restrict__ bias,
    int* __restrict__ cnt, int* __restrict__ slot_token,
    int* __restrict__ pair_slot, float* __restrict__ pair_w,
    __half* __restrict__ xrh)
{
    const int tb = blockIdx.x * 8;
    __shared__ float xs[8][H];
    __shared__ float sc[8][E];
    __shared__ float sb[E];
    const int tid = threadIdx.x;
    const int warp = tid >> 5, lane = tid & 31;

    for (int i = tid; i < 8 * H / 4; i += 256) {
        int row = i >> 8, c4 = i & 255;
        float4 v = ((const float4*)(x + (size_t)(tb + row) * H))[c4];
        ((float4*)xs[row])[c4] = v;
        ((uint2*)(xrh + (size_t)(tb + row) * H))[c4] =
            make_uint2(pack_h2(v.y, v.x), pack_h2(v.w, v.z));
    }
    if (tid < E) sb[tid] = bias[tid];
    __syncthreads();

    for (int q = 0; q < 8; q++) {
        int e = warp * 8 + q;
        const float* wrow = rw + (size_t)e * H;
        float s[8];
        #pragma unroll
        for (int tt = 0; tt < 8; tt++) s[tt] = 0.f;
        for (int i = lane; i < H; i += 32) {
            float wv = wrow[i];
            #pragma unroll
            for (int tt = 0; tt < 8; tt++) s[tt] += xs[tt][i] * wv;
        }
        #pragma unroll
        for (int o = 16; o; o >>= 1)
            #pragma unroll
            for (int tt = 0; tt < 8; tt++) s[tt] += __shfl_xor_sync(0xffffffffu, s[tt], o);
        if (lane == 0) {
            #pragma unroll
            for (int tt = 0; tt < 8; tt++) sc[tt][e] = 1.f / (1.f + expf(-s[tt]));
        }
    }
    __syncthreads();

    if (tid < 8) {
        int t = tb + tid;
        unsigned long long used = 0ull;
        int idx[KTOP]; float tsc[KTOP]; float sum = 0.f;
        #pragma unroll
        for (int k = 0; k < KTOP; k++) {
            float best = -1e30f; int bi = 0;
            for (int e = 0; e < E; e++) {
                if (used & (1ull << e)) continue;
                float v = sc[tid][e] + sb[e];
                if (v > best) { best = v; bi = e; }
            }
            used |= 1ull << bi; idx[k] = bi; tsc[k] = sc[tid][bi]; sum += sc[tid][bi];
        }
        float inv = 1.f / (sum + 1e-20f);
        #pragma unroll
        for (int k = 0; k < KTOP; k++) {
            int e = idx[k];
            int pos = atomicAdd(&cnt[e], 1);
            float w = tsc[k] * inv;
            int slot;
            if (pos < CAP) { slot = e * CAP + pos; slot_token[slot] = t; }
            else           { slot = 0; w = 0.f; }
            pair_slot[t * KTOP + k] = slot;
            pair_w[t * KTOP + k]    = w;
        }
    }
}

// ===== gemm_tc: fp16 A & B (K-major), K-chunk 64, 3-stage ring, 2 CTAs/SM =====
template<bool GATHER, bool GELU, bool HOUT, int NTILE>
__global__ __launch_bounds__(256) void gemm_tc(
    const __half* __restrict__ Aall, long long sAe, int ldA,
    const __half* __restrict__ Ball, long long sBe,
    void* __restrict__ Call, long long sCe, int ldC,
    int Kdim, int Ncols,
    const int* __restrict__ cnts, int Mmax,
    const int* __restrict__ tokall)
{
    const int e  = blockIdx.z;
    const int m0 = blockIdx.y * 128;
    const int n0 = blockIdx.x * NTILE;
    int M = Mmax;
    if (cnts) { M = min(cnts[e], Mmax); if (m0 >= M) return; }
    const __half* B = Ball + (long long)e * sBe;

#if TC_OK
    constexpr int ABYTES = 16384;
    constexpr int BBYTES = NTILE * 128;
    constexpr int STAGE  = ABYTES + BBYTES;
    constexpr int NB     = NTILE / 32;
    constexpr uint32_t IDESC = (NTILE == 256) ? IDESC_H256 : IDESC_H128;

    extern __shared__ char smraw_c[];
    const uint32_t sbase = (smem_u32(smraw_c) + 1023u) & ~1023u;
    const uint32_t ctrl  = sbase + 3 * STAGE;
    const int tid = threadIdx.x, warp = tid >> 5, lane = tid & 31;

    if (warp == 0) { tc_alloc(ctrl, 256); tc_relinquish(); }
    if (tid == 0) {
        #pragma unroll
        for (int j = 0; j < 4; j++) mbar_init(ctrl + 8 + 8 * j, 1);
    }
    __syncthreads();
    uint32_t tmem;
    asm volatile("ld.shared.b32 %0, [%1];" : "=r"(tmem) : "r"(ctrl));

    const __half* aptr[4]; uint32_t a_sts[4], a_ok[4];
    #pragma unroll
    for (int j = 0; j < 4; j++) {
        int g = tid + j * 256;
        int m = g >> 3, k8 = (g & 7) * 8;
        a_sts[j] = sw128(m * 128 + k8 * 2);
        if (GATHER) {
            int tok = (m0 + m < M) ? tokall[e * CAP + m0 + m] : -1;
            a_ok[j] = (tok >= 0) ? 16u : 0u;
            aptr[j] = (tok >= 0) ? (Aall + (long long)tok * ldA + k8) : Aall;
        } else {
            a_ok[j] = 16u;
            aptr[j] = Aall + (long long)e * sAe + (long long)(m0 + m) * ldA + k8;
        }
    }
    const __half* bptr[NB]; uint32_t b_sts[NB];
    #pragma unroll
    for (int j = 0; j < NB; j++) {
        int g = tid + j * 256;
        int n = g >> 3, k8 = (g & 7) * 8;
        b_sts[j] = sw128(n * 128 + k8 * 2);
        bptr[j]  = B + (long long)(n0 + n) * Kdim + k8;
    }
    const int ntiles = Kdim >> 6;

    auto issue = [&](int it) {
        uint32_t base = sbase + (uint32_t)(it % 3) * STAGE;
        long long ka = (long long)it * 64;
        #pragma unroll
        for (int j = 0; j < 4; j++) cpasync16(base + a_sts[j], aptr[j] + ka, a_ok[j]);
        #pragma unroll
        for (int j = 0; j < NB; j++) cpasync16(base + ABYTES + b_sts[j], bptr[j] + ka, 16u);
    };

    issue(0); cp_commit();
    issue(1); cp_commit();
    issue(2); cp_commit();

    for (int it = 0; it < ntiles; ++it) {
        cp_wait2();                 // loads(it) retired
        __syncthreads();
        if (warp == 0 && elect_one()) {
            fence_async();
            uint32_t sa = sbase + (uint32_t)(it % 3) * STAGE;
            uint64_t ad = DESCK | ((sa >> 4) & 0x3FFFu);
            uint64_t bd = DESCK | (((sa + ABYTES) >> 4) & 0x3FFFu);
            #pragma unroll
            for (int s = 0; s < 4; s++)
                mma_f16_ss(tmem, ad + 2 * s, bd + 2 * s, IDESC, (it | s) != 0);
            tc_commit(ctrl + 8 + 8 * (it & 3));
        }
        if (it + 3 < ntiles) {
            mbar_wait(ctrl + 8 + 8 * (it & 3), (it >> 2) & 1);   // MMA(it) done -> buf it%3 free
            issue(it + 3);
        }
        cp_commit();
    }
    { int p = ntiles - 1; mbar_wait(ctrl + 8 + 8 * (p & 3), (p >> 2) & 1); }
    tc_fence_after();

    {
        const int w4 = warp & 3, half = warp >> 2;
        const int row = m0 + w4 * 32 + lane;
        #pragma unroll
        for (int i = 0; i < NTILE / 64; i++) {
            int c0 = half * (NTILE / 2) + i * 32;
            uint32_t r[32];
            ldtm32(r, tmem + c0);
            tc_wait_ld();
            float fv[32];
            #pragma unroll
            for (int q = 0; q < 32; q++) {
                float v = __uint_as_float(r[q]);
                fv[q] = GELU ? gelu_tanh(v) : v;
            }
            if (HOUT) {
                __half* crow = (__half*)Call + (long long)e * sCe + (long long)row * ldC + n0;
                #pragma unroll
                for (int q = 0; q < 4; q++) {
                    uint4 o = make_uint4(
                        pack_h2(fv[q*8+1], fv[q*8+0]), pack_h2(fv[q*8+3], fv[q*8+2]),
                        pack_h2(fv[q*8+5], fv[q*8+4]), pack_h2(fv[q*8+7], fv[q*8+6]));
                    *(uint4*)(crow + c0 + q * 8) = o;
                }
            } else {
                float* crow = (float*)Call + (long long)e * sCe + (long long)row * ldC + n0;
                #pragma unroll
                for (int q = 0; q < 8; q++)
                    *(float4*)(crow + c0 + q * 4) =
                        make_float4(fv[q*4], fv[q*4+1], fv[q*4+2], fv[q*4+3]);
            }
        }
    }
    __syncthreads();
    if (warp == 0) tc_dealloc(tmem, 256);
#else
    const int tid = threadIdx.x;
    const int row = m0 + (tid >> 1);
    const int nh  = (tid & 1) * (NTILE / 2);
    const __half* arow;
    if (GATHER) {
        int tok = (row < M) ? tokall[e * CAP + row] : -1;
        arow = (tok >= 0) ? (Aall + (long long)tok * ldA) : nullptr;
    } else arow = Aall + (long long)e * sAe + (long long)row * ldA;
    for (int c = 0; c < NTILE / 64; c++) {
        float acc[32];
        #pragma unroll
        for (int q = 0; q < 32; q++) acc[q] = 0.f;
        int nb = n0 + nh + c * 32;
        for (int k = 0; k < Kdim; k++) {
            float a = arow ? __half2float(arow[k]) : 0.f;
            for (int q = 0; q < 32; q++)
                acc[q] += a * __half2float(B[(long long)(nb + q) * Kdim + k]);
        }
        for (int q = 0; q < 32; q++) {
            float v = acc[q];
            if (GELU) v = gelu_tanh(v);
            if (HOUT) ((__half*)Call)[(long long)e * sCe + (long long)row * ldC + nb + q] = __float2half(v);
            else      ((float*)Call)[(long long)e * sCe + (long long)row * ldC + nb + q] = v;
        }
    }
#endif
}

__global__ __launch_bounds__(256) void combine_kernel(
    float* __restrict__ out, const __half* __restrict__ y,
    const int* __restrict__ pair_slot, const float* __restrict__ pair_w)
{
    int t = blockIdx.x;
    int slot[KTOP]; float w[KTOP];
    #pragma unroll
    for (int k = 0; k < KTOP; k++) {
        slot[k] = pair_slot[t * KTOP + k];
        w[k]    = pair_w[t * KTOP + k];
    }
    int h4 = threadIdx.x;
    float4 acc = *(float4*)(out + (size_t)t * H + h4 * 4);
    #pragma unroll
    for (int k = 0; k < KTOP; k++) {
        uint2 p = *(const uint2*)(y + (size_t)slot[k] * H + h4 * 4);
        __half2 a = *(__half2*)&p.x, b = *(__half2*)&p.y;
        acc.x += w[k] * __low2float(a);  acc.y += w[k] * __high2float(a);
        acc.z += w[k] * __low2float(b);  acc.w += w[k] * __high2float(b);
    }
    *(float4*)(out + (size_t)t * H + h4 * 4) = acc;
}

extern "C" void kernel_launch(void* const* d_in, const int* in_sizes, int n_in,
                              void* d_out, int out_size)
{
    const float* x   = (const float*)d_in[0];
    const float* rw  = (const float*)d_in[1];
    const float* eb  = (const float*)d_in[2];
    const float* w1  = (const float*)d_in[3];
    const float* w2  = (const float*)d_in[4];
    const float* sw1 = (const float*)d_in[5];
    const float* sw2 = (const float*)d_in[6];
    float* out = (float*)d_out;

    void *pcnt, *ptok, *pps, *ppw, *pmid, *py, *psmid, *pxr, *ps1, *ps2, *pw1t, *pw2t;
    cudaGetSymbolAddress(&pcnt,  g_cnt);
    cudaGetSymbolAddress(&ptok,  g_slot_token);
    cudaGetSymbolAddress(&pps,   g_pair_slot);
    cudaGetSymbolAddress(&ppw,   g_pair_w);
    cudaGetSymbolAddress(&pmid,  g_midh);
    cudaGetSymbolAddress(&py,    g_yh);
    cudaGetSymbolAddress(&psmid, g_smidh);
    cudaGetSymbolAddress(&pxr,   g_xrh);
    cudaGetSymbolAddress(&ps1,   g_sw1h);
    cudaGetSymbolAddress(&ps2,   g_sw2h);
    cudaGetSymbolAddress(&pw1t,  g_w1th);
    cudaGetSymbolAddress(&pw2t,  g_w2th);

    int*    cnt       = (int*)pcnt;
    int*    slot_tok  = (int*)ptok;
    int*    pair_slot = (int*)pps;
    float*  pair_w    = (float*)ppw;
    __half* midh      = (__half*)pmid;
    __half* yh        = (__half*)py;
    __half* smidh     = (__half*)psmid;
    __half* xrh       = (__half*)pxr;
    __half* sw1h      = (__half*)ps1;
    __half* sw2h      = (__half*)ps2;
    __half* w1th      = (__half*)pw1t;
    __half* w2th      = (__half*)pw2t;

    const int SM128 = 3 * (16384 + 128 * 128) + 1024 + 64;   // 99392 -> 2 CTAs/SM

    static cudaStream_t s1 = nullptr, s2 = nullptr;
    static cudaEvent_t evF, evW1, evW2, evR, evS;
    if (!s1) {
        cudaStreamCreateWithFlags(&s1, cudaStreamNonBlocking);
        cudaStreamCreateWithFlags(&s2, cudaStreamNonBlocking);
        cudaEventCreateWithFlags(&evF,  cudaEventDisableTiming);
        cudaEventCreateWithFlags(&evW1, cudaEventDisableTiming);
        cudaEventCreateWithFlags(&evW2, cudaEventDisableTiming);
        cudaEventCreateWithFlags(&evR,  cudaEventDisableTiming);
        cudaEventCreateWithFlags(&evS,  cudaEventDisableTiming);
        cudaFuncSetAttribute(gemm_tc<true,  true,  true,  128>, cudaFuncAttributeMaxDynamicSharedMemorySize, SM128);
        cudaFuncSetAttribute(gemm_tc<false, false, true,  128>, cudaFuncAttributeMaxDynamicSharedMemorySize, SM128);
        cudaFuncSetAttribute(gemm_tc<false, true,  true,  128>, cudaFuncAttributeMaxDynamicSharedMemorySize, SM128);
        cudaFuncSetAttribute(gemm_tc<false, false, false, 128>, cudaFuncAttributeMaxDynamicSharedMemorySize, SM128);
    }

    zero_cnt_kernel<<<1, 64>>>(cnt);
    cudaEventRecord(evF, 0);
    cudaStreamWaitEvent(s1, evF, 0);
    cudaStreamWaitEvent(s2, evF, 0);

    router2_kernel<<<T / 8, 256>>>(x, rw, eb, cnt, slot_tok, pair_slot, pair_w, xrh);
    cudaEventRecord(evR, 0);

    tcvt_kernel<<<dim3(F / 128, H / 32, E), 256, 0, s1>>>(w1, w1th, H, F);
    cudaEventRecord(evW1, s1);

    cudaStreamWaitEvent(0, evW1, 0);
    gemm_tc<true, true, true, 128><<<dim3(F / 128, CAP / 128, E), 256, SM128>>>(
        xrh, 0LL, H, w1th, (long long)F * H,
        midh, (long long)CAP * F, F, H, F, cnt, CAP, slot_tok);

    tcvt_kernel<<<dim3(H / 128, F / 32, E), 256, 0, s1>>>(w2, w2th, F, H);
    cudaEventRecord(evW2, s1);

    cudaStreamWaitEvent(0, evW2, 0);
    gemm_tc<false, false, true, 128><<<dim3(H / 128, CAP / 128, E), 256, SM128>>>(
        midh, (long long)CAP * F, F, w2th, (long long)H * F,
        yh, (long long)CAP * H, H, F, H, cnt, CAP, slot_tok);

    prep_kernel<<<SF * H / 4 / 256, 256, 0, s2>>>(sw1, sw1h, sw2, sw2h);
    cudaStreamWaitEvent(s2, evR, 0);
    gemm_tc<false, true, true, 128><<<dim3(SF / 128, T / 128, 1), 256, SM128, s2>>>(
        xrh, 0LL, H, sw1h, 0LL, smidh, 0LL, SF, H, SF, nullptr, T, nullptr);
    gemm_tc<false, false, false, 128><<<dim3(H / 128, T / 128, 1), 256, SM128, s2>>>(
        smidh, 0LL, SF, sw2h, 0LL, out, 0LL, H, SF, H, nullptr, T, nullptr);
    cudaEventRecord(evS, s2);

    cudaStreamWaitEvent(0, evS, 0);
    combine_kernel<<<T, 256>>>(out, yh, pair_slot, pair_w);
}

// round 17
// speedup vs baseline: 1.0796x; 1.0494x over previous
#include <cuda_runtime.h>
#include <cuda.h>
#include <cuda_fp16.h>
#include <math.h>
#include <stdint.h>

#define E    64
#define KTOP 6
#define H    1024
#define F    512
#define SF   2048
#define T    2048
#define CAP  384

#if !defined(__CUDA_ARCH__) || defined(__CUDA_ARCH_FEAT_SM103_ALL) || \
    defined(__CUDA_ARCH_FEAT_SM100_ALL) || defined(__CUDA_ARCH_FEAT_SM101_ALL) || \
    defined(__CUDA_ARCH_SPECIFIC__)
#define TC_OK 1
#else
#define TC_OK 0
#endif

__device__ int    g_cnt[E];
__device__ int    g_slot_token[E * CAP];
__device__ int    g_pair_slot[T * KTOP];
__device__ float  g_pair_w[T * KTOP];
__device__ __half g_midh[(size_t)E * CAP * F];
__device__ __half g_yh[(size_t)E * CAP * H];
__device__ __half g_smidh[(size_t)T * SF];
__device__ __half g_xrh[(size_t)T * H];
__device__ __half g_sw1h[(size_t)SF * H];
__device__ __half g_sw2h[(size_t)H * SF];
__device__ __half g_w1th[(size_t)E * F * H];
__device__ __half g_w2th[(size_t)E * H * F];

__device__ __forceinline__ float gelu_tanh(float x) {
    float u = 0.7978845608028654f * (x + 0.044715f * x * x * x);
    return 0.5f * x * (1.0f + tanhf(u));
}
__device__ __forceinline__ uint32_t pack_h2(float hi, float lo) {
    uint32_t r;
    asm("cvt.rn.f16x2.f32 %0, %1, %2;" : "=r"(r) : "f"(hi), "f"(lo));
    return r;
}

#if TC_OK
__device__ __forceinline__ uint32_t smem_u32(const void* p) {
    uint32_t a;
    asm("{ .reg .u64 t; cvta.to.shared.u64 t, %1; cvt.u32.u64 %0, t; }" : "=r"(a) : "l"(p));
    return a;
}
__device__ __forceinline__ uint32_t elect_one() {
    uint32_t pred;
    asm volatile("{\n\t.reg .pred p;\n\telect.sync _|p, 0xFFFFFFFF;\n\tselp.b32 %0, 1, 0, p;\n\t}" : "=r"(pred));
    return pred;
}
__device__ __forceinline__ void cpasync16(uint32_t dst, const void* src, uint32_t sz) {
    asm volatile("cp.async.cg.shared.global [%0], [%1], 16, %2;" :: "r"(dst), "l"(src), "r"(sz) : "memory");
}
__device__ __forceinline__ void cp_commit() { asm volatile("cp.async.commit_group;" ::: "memory"); }
__device__ __forceinline__ void cp_wait1()  { asm volatile("cp.async.wait_group 1;" ::: "memory"); }
__device__ __forceinline__ void mbar_init(uint32_t mbar, uint32_t cnt) {
    asm volatile("mbarrier.init.shared.b64 [%0], %1;" :: "r"(mbar), "r"(cnt) : "memory");
}
__device__ __forceinline__ void mbar_arrive(uint32_t mbar) {
    asm volatile("mbarrier.arrive.shared.b64 _, [%0];" :: "r"(mbar) : "memory");
}
__device__ __forceinline__ void mbar_expect(uint32_t mbar, uint32_t bytes) {
    asm volatile("mbarrier.arrive.expect_tx.shared.b64 _, [%0], %1;" :: "r"(mbar), "r"(bytes) : "memory");
}
__device__ __forceinline__ void mbar_wait(uint32_t mbar, uint32_t parity) {
    asm volatile(
        "{\n\t.reg .pred P;\nW_%=:\n\t"
        "mbarrier.try_wait.parity.acquire.cta.shared::cta.b64 P, [%0], %1, 0x989680;\n\t"
        "@P bra.uni D_%=;\n\tbra.uni W_%=;\nD_%=:\n\t}"
        :: "r"(mbar), "r"(parity) : "memory");
}
__device__ __forceinline__ void tma2d(uint32_t smem, const CUtensorMap* tm, int x, int y, uint32_t mbar) {
    asm volatile(
        "cp.async.bulk.tensor.2d.shared::cta.global.tile.mbarrier::complete_tx::bytes "
        "[%0], [%1, {%2, %3}], [%4];"
        :: "r"(smem), "l"(tm), "r"(x), "r"(y), "r"(mbar) : "memory");
}
__device__ __forceinline__ void tc_alloc(uint32_t s, uint32_t n) {
    asm volatile("tcgen05.alloc.cta_group::1.sync.aligned.shared::cta.b32 [%0], %1;" :: "r"(s), "r"(n) : "memory");
}
__device__ __forceinline__ void tc_relinquish() {
    asm volatile("tcgen05.relinquish_alloc_permit.cta_group::1.sync.aligned;");
}
__device__ __forceinline__ void tc_dealloc(uint32_t t, uint32_t n) {
    asm volatile("tcgen05.dealloc.cta_group::1.sync.aligned.b32 %0, %1;" :: "r"(t), "r"(n));
}
__device__ __forceinline__ void tc_commit(uint32_t mbar) {
    asm volatile("tcgen05.commit.cta_group::1.mbarrier::arrive::one.shared::cluster.b64 [%0];" :: "r"(mbar) : "memory");
}
__device__ __forceinline__ void fence_async()   { asm volatile("fence.proxy.async.shared::cta;" ::: "memory"); }
__device__ __forceinline__ void tc_fence_after(){ asm volatile("tcgen05.fence::after_thread_sync;" ::: "memory"); }
__device__ __forceinline__ void tc_wait_ld()    { asm volatile("tcgen05.wait::ld.sync.aligned;" ::: "memory"); }
__device__ __forceinline__ void mma_f16_ss(uint32_t d, uint64_t ad, uint64_t bd, uint32_t idesc, uint32_t en) {
    asm volatile(
        "{\n\t.reg .pred p;\n\tsetp.ne.u32 p, %5, 0;\n\t"
        "tcgen05.mma.cta_group::1.kind::f16 [%0], %1, %2, %3, {%4, %4, %4, %4}, p;\n\t}"
        :: "r"(d), "l"(ad), "l"(bd), "r"(idesc), "r"(0u), "r"(en) : "memory");
}
__device__ __forceinline__ void ldtm32(uint32_t* r, uint32_t addr) {
    asm volatile(
        "tcgen05.ld.sync.aligned.32x32b.x32.b32 "
        "{%0, %1, %2, %3, %4, %5, %6, %7, %8, %9, %10, %11, %12, %13, %14, %15, "
        "%16, %17, %18, %19, %20, %21, %22, %23, %24, %25, %26, %27, %28, %29, %30, %31}, [%32];"
        : "=r"(r[0]), "=r"(r[1]), "=r"(r[2]), "=r"(r[3]), "=r"(r[4]), "=r"(r[5]), "=r"(r[6]), "=r"(r[7]),
          "=r"(r[8]), "=r"(r[9]), "=r"(r[10]), "=r"(r[11]), "=r"(r[12]), "=r"(r[13]), "=r"(r[14]), "=r"(r[15]),
          "=r"(r[16]), "=r"(r[17]), "=r"(r[18]), "=r"(r[19]), "=r"(r[20]), "=r"(r[21]), "=r"(r[22]), "=r"(r[23]),
          "=r"(r[24]), "=r"(r[25]), "=r"(r[26]), "=r"(r[27]), "=r"(r[28]), "=r"(r[29]), "=r"(r[30]), "=r"(r[31])
        : "r"(addr));
}
__device__ __forceinline__ uint32_t sw128(uint32_t b) { return b ^ ((b >> 3) & 0x70); }
#define DESCK      0x4000404000010000ull
#define IDESC_H256 0x8400010u
#define IDESC_H128 0x8200010u
#endif

__global__ void zero_cnt_kernel(int* cnt) {
    if (threadIdx.x < E) cnt[threadIdx.x] = 0;
}

__global__ __launch_bounds__(256) void tcvt_kernel(
    const float* __restrict__ src, __half* __restrict__ dst, int R, int Cc)
{
    __shared__ float tile[32][133];
    int e = blockIdx.z;
    const float* S = src + (size_t)e * R * Cc;
    __half*      D = dst + (size_t)e * R * Cc;
    int r0 = blockIdx.y * 32, c0 = blockIdx.x * 128;
    int tx = threadIdx.x & 31, ty = threadIdx.x >> 5;
    #pragma unroll
    for (int i = 0; i < 4; i++) {
        int r = ty + 8 * i;
        float4 v = *(const float4*)(S + (size_t)(r0 + r) * Cc + c0 + tx * 4);
        tile[r][tx * 4 + 0] = v.x; tile[r][tx * 4 + 1] = v.y;
        tile[r][tx * 4 + 2] = v.z; tile[r][tx * 4 + 3] = v.w;
    }
    __syncthreads();
    int rx = threadIdx.x & 7, cy = threadIdx.x >> 3;
    #pragma unroll
    for (int i = 0; i < 4; i++) {
        int c = cy + 32 * i;
        uint2 o = make_uint2(
            pack_h2(tile[rx * 4 + 1][c], tile[rx * 4 + 0][c]),
            pack_h2(tile[rx * 4 + 3][c], tile[rx * 4 + 2][c]));
        *(uint2*)(D + (size_t)(c0 + c) * R + r0 + rx * 4) = o;
    }
}

__global__ __launch_bounds__(256) void prep_kernel(
    const float* __restrict__ sw1, __half* __restrict__ sw1h,
    const float* __restrict__ sw2, __half* __restrict__ sw2h)
{
    int i = blockIdx.x * 256 + threadIdx.x;
    float4 a = ((const float4*)sw1)[i];
    ((uint2*)sw1h)[i] = make_uint2(pack_h2(a.y, a.x), pack_h2(a.w, a.z));
    float4 b = ((const float4*)sw2)[i];
    ((uint2*)sw2h)[i] = make_uint2(pack_h2(b.y, b.x), pack_h2(b.w, b.z));
}

__global__ __launch_bounds__(256) void router2_kernel(
    const float* __restrict__ x, const float* __restrict__ rw,
    const float* __restrict__ bias,
    int* __restrict__ cnt, int* __restrict__ slot_token,
    int* __restrict__ pair_slot, float* __restrict__ pair_w,
    __half* __restrict__ xrh)
{
    const int tb = blockIdx.x * 8;
    __shared__ float xs[8][H];
    __shared__ float sc[8][E];
    __shared__ float sb[E];
    const int tid = threadIdx.x;
    const int warp = tid >> 5, lane = tid & 31;

    for (int i = tid; i < 8 * H / 4; i += 256) {
        int row = i >> 8, c4 = i & 255;
        float4 v = ((const float4*)(x + (size_t)(tb + row) * H))[c4];
        ((float4*)xs[row])[c4] = v;
        ((uint2*)(xrh + (size_t)(tb + row) * H))[c4] =
            make_uint2(pack_h2(v.y, v.x), pack_h2(v.w, v.z));
    }
    if (tid < E) sb[tid] = bias[tid];
    __syncthreads();

    for (int q = 0; q < 8; q++) {
        int e = warp * 8 + q;
        const float* wrow = rw + (size_t)e * H;
        float s[8];
        #pragma unroll
        for (int tt = 0; tt < 8; tt++) s[tt] = 0.f;
        for (int i = lane; i < H; i += 32) {
            float wv = wrow[i];
            #pragma unroll
            for (int tt = 0; tt < 8; tt++) s[tt] += xs[tt][i] * wv;
        }
        #pragma unroll
        for (int o = 16; o; o >>= 1)
            #pragma unroll
            for (int tt = 0; tt < 8; tt++) s[tt] += __shfl_xor_sync(0xffffffffu, s[tt], o);
        if (lane == 0) {
            #pragma unroll
            for (int tt = 0; tt < 8; tt++) sc[tt][e] = 1.f / (1.f + expf(-s[tt]));
        }
    }
    __syncthreads();

    if (tid < 8) {
        int t = tb + tid;
        unsigned long long used = 0ull;
        int idx[KTOP]; float tsc[KTOP]; float sum = 0.f;
        #pragma unroll
        for (int k = 0; k < KTOP; k++) {
            float best = -1e30f; int bi = 0;
            for (int e = 0; e < E; e++) {
                if (used & (1ull << e)) continue;
                float v = sc[tid][e] + sb[e];
                if (v > best) { best = v; bi = e; }
            }
            used |= 1ull << bi; idx[k] = bi; tsc[k] = sc[tid][bi]; sum += sc[tid][bi];
        }
        float inv = 1.f / (sum + 1e-20f);
        #pragma unroll
        for (int k = 0; k < KTOP; k++) {
            int e = idx[k];
            int pos = atomicAdd(&cnt[e], 1);
            float w = tsc[k] * inv;
            int slot;
            if (pos < CAP) { slot = e * CAP + pos; slot_token[slot] = t; }
            else           { slot = 0; w = 0.f; }
            pair_slot[t * KTOP + k] = slot;
            pair_w[t * KTOP + k]    = w;
        }
    }
}

template<bool GELU, bool HOUT, int NTILE>
__device__ __forceinline__ void epilogue_tc(
    uint32_t tmem, int warp, int lane, int e, int m0, int n0,
    void* Call, long long sCe, int ldC)
{
#if TC_OK
    const int w4 = warp & 3, half = warp >> 2;
    const int row = m0 + w4 * 32 + lane;
    #pragma unroll
    for (int i = 0; i < NTILE / 64; i++) {
        int c0 = half * (NTILE / 2) + i * 32;
        uint32_t r[32];
        ldtm32(r, tmem + c0);
        tc_wait_ld();
        float fv[32];
        #pragma unroll
        for (int q = 0; q < 32; q++) {
            float v = __uint_as_float(r[q]);
            fv[q] = GELU ? gelu_tanh(v) : v;
        }
        if (HOUT) {
            __half* crow = (__half*)Call + (long long)e * sCe + (long long)row * ldC + n0;
            #pragma unroll
            for (int q = 0; q < 4; q++) {
                uint4 o = make_uint4(
                    pack_h2(fv[q*8+1], fv[q*8+0]), pack_h2(fv[q*8+3], fv[q*8+2]),
                    pack_h2(fv[q*8+5], fv[q*8+4]), pack_h2(fv[q*8+7], fv[q*8+6]));
                *(uint4*)(crow + c0 + q * 8) = o;
            }
        } else {
            float* crow = (float*)Call + (long long)e * sCe + (long long)row * ldC + n0;
            #pragma unroll
            for (int q = 0; q < 8; q++)
                *(float4*)(crow + c0 + q * 4) =
                    make_float4(fv[q*4], fv[q*4+1], fv[q*4+2], fv[q*4+3]);
        }
    }
#endif
}

// ===== pure-TMA GEMM. done-mbar (index S+4) guards epilogue; only elected
// thread waits mma mbars, strictly in order (parity-safe). =====
template<bool GELU, bool HOUT, int NTILE, int S>
__global__ __launch_bounds__(256) void gemm_tma(
    const __grid_constant__ CUtensorMap tmA,
    const __grid_constant__ CUtensorMap tmB,
    int aRowsPerE, int bRowsPerE,
    void* Call, long long sCe, int ldC, int Kdim,
    const int* cnts, int Mmax,
    const __half* fbA, int ldA, long long sAe,
    const __half* fbB, long long sBe)
{
    const int e  = blockIdx.z;
    const int m0 = blockIdx.y * 128;
    const int n0 = blockIdx.x * NTILE;
    int M = Mmax;
    if (cnts) { M = min(cnts[e], Mmax); if (m0 >= M) return; }

#if TC_OK
    constexpr int ABYTES = 16384;
    constexpr int BBYTES = NTILE * 128;
    constexpr int STAGE  = ABYTES + BBYTES;
    constexpr uint32_t TX = (uint32_t)STAGE;
    constexpr uint32_t IDESC = (NTILE == 256) ? IDESC_H256 : IDESC_H128;

    extern __shared__ char smraw_t[];
    const uint32_t sbase = (smem_u32(smraw_t) + 1023u) & ~1023u;
    const uint32_t ctrl  = sbase + S * STAGE;
    const uint32_t done  = ctrl + 8 + 8 * (S + 4);
    const int tid = threadIdx.x, warp = tid >> 5, lane = tid & 31;

    if (warp == 0) { tc_alloc(ctrl, 256); tc_relinquish(); }
    if (tid == 0) {
        #pragma unroll
        for (int j = 0; j < S + 5; j++) mbar_init(ctrl + 8 + 8 * j, 1);
    }
    __syncthreads();
    uint32_t tmem;
    asm volatile("ld.shared.b32 %0, [%1];" : "=r"(tmem) : "r"(ctrl));

    const int aRow0 = e * aRowsPerE + m0;
    const int bRow0 = e * bRowsPerE + n0;
    const int ntiles = Kdim >> 6;

    if (warp == 0 && elect_one()) {
        #pragma unroll
        for (int s = 0; s < S; s++) {
            mbar_expect(ctrl + 8 + 8 * s, TX);
            tma2d(sbase + s * STAGE,          &tmA, s * 64, aRow0, ctrl + 8 + 8 * s);
            tma2d(sbase + s * STAGE + ABYTES, &tmB, s * 64, bRow0, ctrl + 8 + 8 * s);
        }
        for (int it = 0; it < ntiles; ++it) {
            const int b = it % S;
            mbar_wait(ctrl + 8 + 8 * b, (it / S) & 1);
            uint32_t sa = sbase + b * STAGE;
            uint64_t ad = DESCK | ((sa >> 4) & 0x3FFFu);
            uint64_t bd = DESCK | (((sa + ABYTES) >> 4) & 0x3FFFu);
            #pragma unroll
            for (int s = 0; s < 4; s++)
                mma_f16_ss(tmem, ad + 2 * s, bd + 2 * s, IDESC, (it | s) != 0);
            tc_commit(ctrl + 8 + 8 * (S + (it & 3)));
            if (it + S < ntiles) {
                mbar_wait(ctrl + 8 + 8 * (S + (it & 3)), (it >> 2) & 1);
                mbar_expect(ctrl + 8 + 8 * b, TX);
                tma2d(sbase + b * STAGE,          &tmA, (it + S) * 64, aRow0, ctrl + 8 + 8 * b);
                tma2d(sbase + b * STAGE + ABYTES, &tmB, (it + S) * 64, bRow0, ctrl + 8 + 8 * b);
            }
        }
        // in-order tail waits for the last S iterations' MMAs, then signal done
        for (int q = (ntiles > S ? ntiles - S : 0); q < ntiles; ++q)
            mbar_wait(ctrl + 8 + 8 * (S + (q & 3)), (q >> 2) & 1);
        mbar_arrive(done);
    }
    mbar_wait(done, 0);
    tc_fence_after();
    epilogue_tc<GELU, HOUT, NTILE>(tmem, warp, lane, e, m0, n0, Call, sCe, ldC);
    __syncthreads();
    if (warp == 0) tc_dealloc(tmem, 256);
#else
    const int tid = threadIdx.x;
    const int row = m0 + (tid >> 1);
    const int nh  = (tid & 1) * (NTILE / 2);
    const __half* arow = fbA + (long long)e * sAe + (long long)row * ldA;
    const __half* B = fbB + (long long)e * sBe;
    for (int c = 0; c < NTILE / 64; c++) {
        float acc[32];
        #pragma unroll
        for (int q = 0; q < 32; q++) acc[q] = 0.f;
        int nb = n0 + nh + c * 32;
        for (int k = 0; k < Kdim; k++) {
            float a = __half2float(arow[k]);
            for (int q = 0; q < 32; q++)
                acc[q] += a * __half2float(B[(long long)(nb + q) * Kdim + k]);
        }
        for (int q = 0; q < 32; q++) {
            float v = acc[q];
            if (GELU) v = gelu_tanh(v);
            if (HOUT) ((__half*)Call)[(long long)e * sCe + (long long)row * ldC + nb + q] = __float2half(v);
            else      ((float*)Call)[(long long)e * sCe + (long long)row * ldC + nb + q] = v;
        }
    }
#endif
}

// ===== gather GEMM: A via cp.async, B via TMA; same done-mbar protocol =====
template<bool GELU, bool HOUT, int NTILE>
__global__ __launch_bounds__(256) void gemm_tma_ga(
    const __half* __restrict__ Aall, int ldA,
    const __grid_constant__ CUtensorMap tmB,
    int bRowsPerE,
    void* Call, long long sCe, int ldC, int Kdim,
    const int* cnts, int Mmax, const int* tokall,
    const __half* fbB, long long sBe)
{
    const int e  = blockIdx.z;
    const int m0 = blockIdx.y * 128;
    const int n0 = blockIdx.x * NTILE;
    int M = min(cnts[e], Mmax);
    if (m0 >= M) return;

#if TC_OK
    constexpr int SS = 2;
    constexpr int ABYTES = 16384;
    constexpr int BBYTES = NTILE * 128;
    constexpr int STAGE  = ABYTES + BBYTES;
    constexpr uint32_t IDESC = (NTILE == 256) ? IDESC_H256 : IDESC_H128;

    extern __shared__ char smraw_g[];
    const uint32_t sbase = (smem_u32(smraw_g) + 1023u) & ~1023u;
    const uint32_t ctrl  = sbase + SS * STAGE;
    const uint32_t done  = ctrl + 8 + 8 * (SS + 4);
    const int tid = threadIdx.x, warp = tid >> 5, lane = tid & 31;

    if (warp == 0) { tc_alloc(ctrl, 256); tc_relinquish(); }
    if (tid == 0) {
        #pragma unroll
        for (int j = 0; j < SS + 5; j++) mbar_init(ctrl + 8 + 8 * j, 1);
    }
    __syncthreads();
    uint32_t tmem;
    asm volatile("ld.shared.b32 %0, [%1];" : "=r"(tmem) : "r"(ctrl));

    const __half* aptr[4]; uint32_t a_sts[4], a_ok[4];
    #pragma unroll
    for (int j = 0; j < 4; j++) {
        int g = tid + j * 256;
        int m = g >> 3, k8 = (g & 7) * 8;
        a_sts[j] = sw128(m * 128 + k8 * 2);
        int tok = (m0 + m < M) ? tokall[e * CAP + m0 + m] : -1;
        a_ok[j] = (tok >= 0) ? 16u : 0u;
        aptr[j] = (tok >= 0) ? (Aall + (long long)tok * ldA + k8) : Aall;
    }
    const int bRow0 = e * bRowsPerE + n0;
    const int ntiles = Kdim >> 6;

    auto issueA = [&](int it) {
        uint32_t base = sbase + (it & 1) * STAGE;
        long long ka = (long long)it * 64;
        #pragma unroll
        for (int j = 0; j < 4; j++) cpasync16(base + a_sts[j], aptr[j] + ka, a_ok[j]);
    };

    if (warp == 0 && elect_one()) {
        #pragma unroll
        for (int s = 0; s < SS; s++) {
            mbar_expect(ctrl + 8 + 8 * s, (uint32_t)BBYTES);
            tma2d(sbase + s * STAGE + ABYTES, &tmB, s * 64, bRow0, ctrl + 8 + 8 * s);
        }
    }
    issueA(0); cp_commit();
    issueA(1); cp_commit();

    for (int it = 0; it < ntiles; ++it) {
        const int b = it & 1;
        cp_wait1();
        __syncthreads();
        if (warp == 0 && elect_one()) {
            fence_async();
            mbar_wait(ctrl + 8 + 8 * b, (it >> 1) & 1);
            uint32_t sa = sbase + b * STAGE;
            uint64_t ad = DESCK | ((sa >> 4) & 0x3FFFu);
            uint64_t bd = DESCK | (((sa + ABYTES) >> 4) & 0x3FFFu);
            #pragma unroll
            for (int s = 0; s < 4; s++)
                mma_f16_ss(tmem, ad + 2 * s, bd + 2 * s, IDESC, (it | s) != 0);
            tc_commit(ctrl + 8 + 8 * (SS + (it & 3)));
            if (it + SS < ntiles) {
                mbar_wait(ctrl + 8 + 8 * (SS + (it & 3)), (it >> 2) & 1);
                mbar_expect(ctrl + 8 + 8 * b, (uint32_t)BBYTES);
                tma2d(sbase + b * STAGE + ABYTES, &tmB, (it + SS) * 64, bRow0, ctrl + 8 + 8 * b);
            }
        }
        if (it + SS < ntiles) {
            __syncthreads();            // elect waited MMA(it) -> A buffer free
            issueA(it + SS);
        }
        cp_commit();
    }
    if (warp == 0 && elect_one()) {
        for (int q = (ntiles > SS ? ntiles - SS : 0); q < ntiles; ++q)
            mbar_wait(ctrl + 8 + 8 * (SS + (q & 3)), (q >> 2) & 1);
        mbar_arrive(done);
    }
    mbar_wait(done, 0);
    tc_fence_after();
    epilogue_tc<GELU, HOUT, NTILE>(tmem, warp, lane, e, m0, n0, Call, sCe, ldC);
    __syncthreads();
    if (warp == 0) tc_dealloc(tmem, 256);
#else
    const int tid = threadIdx.x;
    const int row = m0 + (tid >> 1);
    const int nh  = (tid & 1) * (NTILE / 2);
    int tok = (row < M) ? tokall[e * CAP + row] : -1;
    const __half* arow = (tok >= 0) ? (Aall + (long long)tok * ldA) : nullptr;
    const __half* B = fbB + (long long)e * sBe;
    for (int c = 0; c < NTILE / 64; c++) {
        float acc[32];
        #pragma unroll
        for (int q = 0; q < 32; q++) acc[q] = 0.f;
        int nb = n0 + nh + c * 32;
        for (int k = 0; k < Kdim; k++) {
            float a = arow ? __half2float(arow[k]) : 0.f;
            for (int q = 0; q < 32; q++)
                acc[q] += a * __half2float(B[(long long)(nb + q) * Kdim + k]);
        }
        for (int q = 0; q < 32; q++) {
            float v = acc[q];
            if (GELU) v = gelu_tanh(v);
            if (HOUT) ((__half*)Call)[(long long)e * sCe + (long long)row * ldC + nb + q] = __float2half(v);
            else      ((float*)Call)[(long long)e * sCe + (long long)row * ldC + nb + q] = v;
        }
    }
#endif
}

__global__ __launch_bounds__(256) void combine_kernel(
    float* __restrict__ out, const __half* __restrict__ y,
    const int* __restrict__ pair_slot, const float* __restrict__ pair_w)
{
    int t = blockIdx.x;
    int slot[KTOP]; float w[KTOP];
    #pragma unroll
    for (int k = 0; k < KTOP; k++) {
        slot[k] = pair_slot[t * KTOP + k];
        w[k]    = pair_w[t * KTOP + k];
    }
    int h4 = threadIdx.x;
    float4 acc = *(float4*)(out + (size_t)t * H + h4 * 4);
    #pragma unroll
    for (int k = 0; k < KTOP; k++) {
        uint2 p = *(const uint2*)(y + (size_t)slot[k] * H + h4 * 4);
        __half2 a = *(__half2*)&p.x, b = *(__half2*)&p.y;
        acc.x += w[k] * __low2float(a);  acc.y += w[k] * __high2float(a);
        acc.z += w[k] * __low2float(b);  acc.w += w[k] * __high2float(b);
    }
    *(float4*)(out + (size_t)t * H + h4 * 4) = acc;
}

// ---------------- host ----------------
typedef CUresult (*tmEncFn)(CUtensorMap*, CUtensorMapDataType, cuuint32_t, void*,
                            const cuuint64_t*, const cuuint64_t*, const cuuint32_t*,
                            const cuuint32_t*, CUtensorMapInterleave, CUtensorMapSwizzle,
                            CUtensorMapL2promotion, CUtensorMapFloatOOBfill);

static void make_tm2d(tmEncFn enc, CUtensorMap* tm, void* ptr,
                      uint64_t inner, uint64_t outer, uint32_t box0, uint32_t box1)
{
    cuuint64_t dims[2]    = {inner, outer};
    cuuint64_t strides[1] = {inner * 2};
    cuuint32_t box[2]     = {box0, box1};
    cuuint32_t es[2]      = {1, 1};
    enc(tm, CU_TENSOR_MAP_DATA_TYPE_FLOAT16, 2, ptr, dims, strides, box, es,
        CU_TENSOR_MAP_INTERLEAVE_NONE, CU_TENSOR_MAP_SWIZZLE_128B,
        CU_TENSOR_MAP_L2_PROMOTION_L2_128B, CU_TENSOR_MAP_FLOAT_OOB_FILL_NONE);
}

extern "C" void kernel_launch(void* const* d_in, const int* in_sizes, int n_in,
                              void* d_out, int out_size)
{
    const float* x   = (const float*)d_in[0];
    const float* rw  = (const float*)d_in[1];
    const float* eb  = (const float*)d_in[2];
    const float* w1  = (const float*)d_in[3];
    const float* w2  = (const float*)d_in[4];
    const float* sw1 = (const float*)d_in[5];
    const float* sw2 = (const float*)d_in[6];
    float* out = (float*)d_out;

    void *pcnt, *ptok, *pps, *ppw, *pmid, *py, *psmid, *pxr, *ps1, *ps2, *pw1t, *pw2t;
    cudaGetSymbolAddress(&pcnt,  g_cnt);
    cudaGetSymbolAddress(&ptok,  g_slot_token);
    cudaGetSymbolAddress(&pps,   g_pair_slot);
    cudaGetSymbolAddress(&ppw,   g_pair_w);
    cudaGetSymbolAddress(&pmid,  g_midh);
    cudaGetSymbolAddress(&py,    g_yh);
    cudaGetSymbolAddress(&psmid, g_smidh);
    cudaGetSymbolAddress(&pxr,   g_xrh);
    cudaGetSymbolAddress(&ps1,   g_sw1h);
    cudaGetSymbolAddress(&ps2,   g_sw2h);
    cudaGetSymbolAddress(&pw1t,  g_w1th);
    cudaGetSymbolAddress(&pw2t,  g_w2th);

    int*    cnt       = (int*)pcnt;
    int*    slot_tok  = (int*)ptok;
    int*    pair_slot = (int*)pps;
    float*  pair_w    = (float*)ppw;
    __half* midh      = (__half*)pmid;
    __half* yh        = (__half*)py;
    __half* smidh     = (__half*)psmid;
    __half* xrh       = (__half*)pxr;
    __half* sw1h      = (__half*)ps1;
    __half* sw2h      = (__half*)ps2;
    __half* w1th      = (__half*)pw1t;
    __half* w2th      = (__half*)pw2t;

    const int SMG = 2 * (16384 + 256 * 128) + 1024 + 128;   // 99456: 2 CTAs/SM
    const int SM2 = 3 * (16384 + 128 * 128) + 1024 + 128;   // 99456

    static cudaStream_t s1 = nullptr, s2 = nullptr;
    static cudaEvent_t evF, evW1, evW2, evR, evS;
    static CUtensorMap tmW1, tmW2, tmMid, tmXr, tmSw1, tmSmid, tmSw2;
    if (!s1) {
        cudaStreamCreateWithFlags(&s1, cudaStreamNonBlocking);
        cudaStreamCreateWithFlags(&s2, cudaStreamNonBlocking);
        cudaEventCreateWithFlags(&evF,  cudaEventDisableTiming);
        cudaEventCreateWithFlags(&evW1, cudaEventDisableTiming);
        cudaEventCreateWithFlags(&evW2, cudaEventDisableTiming);
        cudaEventCreateWithFlags(&evR,  cudaEventDisableTiming);
        cudaEventCreateWithFlags(&evS,  cudaEventDisableTiming);

        tmEncFn enc = nullptr;
        cudaDriverEntryPointQueryResult qr;
        cudaGetDriverEntryPoint("cuTensorMapEncodeTiled", (void**)&enc, cudaEnableDefault, &qr);
        make_tm2d(enc, &tmW1,  w1th,  H,  (uint64_t)E * F,   64, 256);
        make_tm2d(enc, &tmW2,  w2th,  F,  (uint64_t)E * H,   64, 256);
        make_tm2d(enc, &tmMid, midh,  F,  (uint64_t)E * CAP, 64, 128);
        make_tm2d(enc, &tmXr,  xrh,   H,  T,                 64, 128);
        make_tm2d(enc, &tmSw1, sw1h,  H,  SF,                64, 256);
        make_tm2d(enc, &tmSmid,smidh, SF, T,                 64, 128);
        make_tm2d(enc, &tmSw2, sw2h,  SF, H,                 64, 128);

        cudaFuncSetAttribute(gemm_tma_ga<true, true, 256>, cudaFuncAttributeMaxDynamicSharedMemorySize, SMG);
        cudaFuncSetAttribute(gemm_tma<false, true,  256, 2>, cudaFuncAttributeMaxDynamicSharedMemorySize, SMG);
        cudaFuncSetAttribute(gemm_tma<true,  true,  256, 2>, cudaFuncAttributeMaxDynamicSharedMemorySize, SMG);
        cudaFuncSetAttribute(gemm_tma<false, false, 128, 3>, cudaFuncAttributeMaxDynamicSharedMemorySize, SM2);
    }

    zero_cnt_kernel<<<1, 64>>>(cnt);
    cudaEventRecord(evF, 0);
    cudaStreamWaitEvent(s1, evF, 0);
    cudaStreamWaitEvent(s2, evF, 0);

    router2_kernel<<<T / 8, 256>>>(x, rw, eb, cnt, slot_tok, pair_slot, pair_w, xrh);
    cudaEventRecord(evR, 0);

    tcvt_kernel<<<dim3(F / 128, H / 32, E), 256, 0, s1>>>(w1, w1th, H, F);
    cudaEventRecord(evW1, s1);

    cudaStreamWaitEvent(0, evW1, 0);
    gemm_tma_ga<true, true, 256><<<dim3(F / 256, CAP / 128, E), 256, SMG>>>(
        xrh, H, tmW1, F, midh, (long long)CAP * F, F, H,
        cnt, CAP, slot_tok, w1th, (long long)F * H);

    tcvt_kernel<<<dim3(H / 128, F / 32, E), 256, 0, s1>>>(w2, w2th, F, H);
    cudaEventRecord(evW2, s1);

    cudaStreamWaitEvent(0, evW2, 0);
    gemm_tma<false, true, 256, 2><<<dim3(H / 256, CAP / 128, E), 256, SMG>>>(
        tmMid, tmW2, CAP, H, yh, (long long)CAP * H, H, F,
        cnt, CAP, midh, F, (long long)CAP * F, w2th, (long long)H * F);

    prep_kernel<<<SF * H / 4 / 256, 256, 0, s2>>>(sw1, sw1h, sw2, sw2h);
    cudaStreamWaitEvent(s2, evR, 0);
    gemm_tma<true, true, 256, 2><<<dim3(SF / 256, T / 128, 1), 256, SMG, s2>>>(
        tmXr, tmSw1, 0, 0, smidh, 0LL, SF, H,
        nullptr, T, xrh, H, 0LL, sw1h, 0LL);
    gemm_tma<false, false, 128, 3><<<dim3(H / 128, T / 128, 1), 256, SM2, s2>>>(
        tmSmid, tmSw2, 0, 0, out, 0LL, H, SF,
        nullptr, T, smidh, SF, 0LL, sw2h, 0LL);
    cudaEventRecord(evS, s2);

    cudaStreamWaitEvent(0, evS, 0);
    combine_kernel<<<T, 256>>>(out, yh, pair_slot, pair_w);
}